// round 7
// baseline (speedup 1.0000x reference)
#include <cuda_runtime.h>
#include <cuda_bf16.h>
#include <cstdint>

#define JN    24
#define DN    256
#define HN    4
#define DHC   64
#define GPC   2
#define MROWS 48          // 2 graphs x 24 rows, contiguous in x
#define TPB   256
#define EMAX  80
#define HSTR  260         // padded fp32 row stride for h staging
#define AIMG  24576       // one A image: 48 rows x 512B
#define DYN_SMEM (MROWS * HSTR * 4)   // 49920 >= 2*AIMG = 49152

// B fragment images: [term(hi,lo)][n-tile 0..31][k-step 0..15][lane][2 regs]
__device__ uint32_t g_Bfrag[2][32][16][32][2];   // 256 KB

__device__ __forceinline__ uint32_t smem_u32(const void* p) {
    uint32_t a;
    asm("{ .reg .u64 t; cvta.to.shared.u64 t, %1; cvt.u32.u64 %0, t; }" : "=r"(a) : "l"(p));
    return a;
}
__device__ __forceinline__ uint32_t packbf(float a, float b) {
    __nv_bfloat16 ha = __float2bfloat16(a), hb = __float2bfloat16(b);
    return (uint32_t)__bfloat16_as_ushort(ha) | ((uint32_t)__bfloat16_as_ushort(hb) << 16);
}

#define LDMATRIX_X4(r0, r1, r2, r3, addr) \
    asm volatile("ldmatrix.sync.aligned.m8n8.x4.shared.b16 {%0,%1,%2,%3}, [%4];" \
        : "=r"(r0), "=r"(r1), "=r"(r2), "=r"(r3) : "r"(addr))

#define MMA_BF16(acc, a, b0, b1) \
    asm volatile("mma.sync.aligned.m16n8k16.row.col.f32.bf16.bf16.f32 " \
        "{%0,%1,%2,%3}, {%4,%5,%6,%7}, {%8,%9}, {%0,%1,%2,%3};" \
        : "+f"((acc)[0]), "+f"((acc)[1]), "+f"((acc)[2]), "+f"((acc)[3]) \
        : "r"((a)[0]), "r"((a)[1]), "r"((a)[2]), "r"((a)[3]), "r"(b0), "r"(b1))

// ---------------- prep: W -> bf16 hi/lo fragment-linear images ----------------
__global__ void prep_W(const float* __restrict__ W) {
    int idx = blockIdx.x * 256 + threadIdx.x;   // 0..16383 = nt*512 + ks*32 + lane
    int nt = idx >> 9, ks = (idx >> 5) & 15, l = idx & 31;
    int n = nt * 8 + (l >> 2);
#pragma unroll
    for (int r = 0; r < 2; r++) {
        int k = ks * 16 + r * 8 + (l & 3) * 2;
        float v0 = W[(size_t)k * DN + n];
        float v1 = W[(size_t)(k + 1) * DN + n];
        __nv_bfloat16 h0 = __float2bfloat16(v0), h1 = __float2bfloat16(v1);
        g_Bfrag[0][nt][ks][l][r] =
            (uint32_t)__bfloat16_as_ushort(h0) | ((uint32_t)__bfloat16_as_ushort(h1) << 16);
        g_Bfrag[1][nt][ks][l][r] =
            packbf(v0 - __bfloat162float(h0), v1 - __bfloat162float(h1));
    }
}

// ---------------- main fused kernel ----------------
__global__ void __launch_bounds__(TPB, 3) gat_mma_kernel(
    const float* __restrict__ x,
    const float* __restrict__ att_src_g, const float* __restrict__ att_dst_g,
    const float* __restrict__ bias, const int* __restrict__ edge_index,
    float* __restrict__ out, int E0)
{
    extern __shared__ unsigned char dynraw[];
    __shared__ float s_att[2 * DN];
    __shared__ float s_bias[DN];
    __shared__ float s_as[MROWS * HN], s_ad[MROWS * HN];
    __shared__ float s_sc[GPC][EMAX * HN];
    __shared__ int   s_src[EMAX], s_dst[EMAX];
    __shared__ int   s_inc[JN][4], s_cnt[JN];

    const int tid = threadIdx.x;
    const int w = tid >> 5, l = tid & 31;
    const uint32_t dynb = smem_u32(dynraw);
    const int E = E0 + JN;

    // ---- small tensors ----
    for (int i = tid; i < 2 * DN; i += TPB)
        s_att[i] = (i < DN) ? att_src_g[i] : att_dst_g[i - DN];
    for (int i = tid; i < DN; i += TPB) s_bias[i] = bias[i];
    if (tid < E0) { s_src[tid] = edge_index[tid]; s_dst[tid] = edge_index[E0 + tid]; }
    if (tid < JN) { s_src[E0 + tid] = tid; s_dst[E0 + tid] = tid; }

    // ---- convert x -> A_hi / A_lo bf16 images in SMEM (XOR-swizzled) ----
    {
        const float* xg = x + (size_t)blockIdx.x * (MROWS * DN);
#pragma unroll
        for (int i = 0; i < 6; i++) {
            int task = tid + i * TPB;          // 0..1535
            int r = task >> 5, c = task & 31;  // row, 8-float chunk
            const float4 a = *(const float4*)(xg + (size_t)r * DN + c * 8);
            const float4 b = *(const float4*)(xg + (size_t)r * DN + c * 8 + 4);
            float v[8] = {a.x, a.y, a.z, a.w, b.x, b.y, b.z, b.w};
            uint32_t hi[4], lo[4];
#pragma unroll
            for (int p = 0; p < 4; p++) {
                __nv_bfloat16 h0 = __float2bfloat16(v[2 * p]);
                __nv_bfloat16 h1 = __float2bfloat16(v[2 * p + 1]);
                hi[p] = (uint32_t)__bfloat16_as_ushort(h0) |
                        ((uint32_t)__bfloat16_as_ushort(h1) << 16);
                lo[p] = packbf(v[2 * p]     - __bfloat162float(h0),
                               v[2 * p + 1] - __bfloat162float(h1));
            }
            uint32_t off = (uint32_t)r * 512u + (uint32_t)((c ^ (r & 7)) << 4);
            *(uint4*)(dynraw + off)        = make_uint4(hi[0], hi[1], hi[2], hi[3]);
            *(uint4*)(dynraw + AIMG + off) = make_uint4(lo[0], lo[1], lo[2], lo[3]);
        }
    }
    __syncthreads();

    // incoming-edge lists (chain graph: cnt <= 3)
    if (tid < JN) {
        int c = 0;
        for (int e = 0; e < E; e++)
            if (s_dst[e] == tid) { if (c < 4) s_inc[tid][c] = e; c++; }
        s_cnt[tid] = c < 4 ? c : 4;
    }

    // ---- GEMM: warp w owns M=48 rows x 32 columns (n-tiles 4w..4w+3) ----
    float acc[3][4][4];
#pragma unroll
    for (int mt = 0; mt < 3; mt++)
#pragma unroll
        for (int nt = 0; nt < 4; nt++)
            acc[mt][nt][0] = acc[mt][nt][1] = acc[mt][nt][2] = acc[mt][nt][3] = 0.f;

    const uint2* bhp = (const uint2*)&g_Bfrag[0][w * 4][0][l][0];
    const uint2* blp = (const uint2*)&g_Bfrag[1][w * 4][0][l][0];

    const uint32_t arow = (uint32_t)(l & 15);
    const uint32_t abase = dynb + arow * 512u;

#pragma unroll 2
    for (int ks = 0; ks < 16; ks++) {
        // single-buffered B fragment loads for this k-step (L2-resident)
        uint32_t Bh[4][2], Bl[4][2];
#pragma unroll
        for (int nt = 0; nt < 4; nt++) {
            uint2 vh = __ldg(&bhp[nt * 512 + ks * 32]);
            uint2 vl = __ldg(&blp[nt * 512 + ks * 32]);
            Bh[nt][0] = vh.x; Bh[nt][1] = vh.y;
            Bl[nt][0] = vl.x; Bl[nt][1] = vl.y;
        }
        const uint32_t kc = (uint32_t)(ks * 2 + (l >> 4));
        const uint32_t koff = (kc ^ (arow & 7u)) << 4;
#pragma unroll
        for (int mt = 0; mt < 3; mt++) {
            const uint32_t aoff = abase + (uint32_t)(mt * 16) * 512u + koff;
            uint32_t ah[4], al[4];
            LDMATRIX_X4(ah[0], ah[1], ah[2], ah[3], aoff);
#pragma unroll
            for (int nt = 0; nt < 4; nt++) MMA_BF16(acc[mt][nt], ah, Bh[nt][0], Bh[nt][1]);
#pragma unroll
            for (int nt = 0; nt < 4; nt++) MMA_BF16(acc[mt][nt], ah, Bl[nt][0], Bl[nt][1]);
            LDMATRIX_X4(al[0], al[1], al[2], al[3], aoff + AIMG);
#pragma unroll
            for (int nt = 0; nt < 4; nt++) MMA_BF16(acc[mt][nt], al, Bh[nt][0], Bh[nt][1]);
        }
    }
    __syncthreads();   // all warps done reading A images before h overwrite

    // ---- store h to SMEM (row-major, stride HSTR) ----
    float* hb = (float*)dynraw;
    {
        const int gid = l >> 2, tig = l & 3;
#pragma unroll
        for (int mt = 0; mt < 3; mt++) {
#pragma unroll
            for (int nt = 0; nt < 4; nt++) {
                const int col = w * 32 + nt * 8 + 2 * tig;
                float* p0 = hb + (mt * 16 + gid) * HSTR + col;
                float* p1 = hb + (mt * 16 + gid + 8) * HSTR + col;
                p0[0] = acc[mt][nt][0]; p0[1] = acc[mt][nt][1];
                p1[0] = acc[mt][nt][2]; p1[1] = acc[mt][nt][3];
            }
        }
    }
    __syncthreads();

    // ---- attention dots a_s, a_d for all (row, head) ----
    if (tid < MROWS * HN) {
        const int row = tid >> 2, hh = tid & 3;
        const float* hr = hb + row * HSTR + hh * DHC;
        float as = 0.f, ad = 0.f;
#pragma unroll 8
        for (int d = 0; d < DHC; d++) {
            float v = hr[d];
            as += v * s_att[hh * DHC + d];
            ad += v * s_att[DN + hh * DHC + d];
        }
        s_as[tid] = as; s_ad[tid] = ad;
    }
    __syncthreads();

    // ---- per-edge scores with leaky_relu(0.2) ----
    for (int idx = tid; idx < GPC * E * HN; idx += TPB) {
        const int g = idx / (E * HN), rem = idx - g * (E * HN);
        const int e = rem >> 2, hh = rem & 3;
        float sc = s_as[(g * JN + s_src[e]) * HN + hh] + s_ad[(g * JN + s_dst[e]) * HN + hh];
        s_sc[g][e * HN + hh] = (sc >= 0.f) ? sc : 0.2f * sc;
    }
    __syncthreads();

    // ---- segment softmax: alpha written in place into s_sc ----
    if (tid < GPC * JN * HN) {
        const int g = tid / (JN * HN), rem = tid - g * (JN * HN);
        const int j = rem >> 2, hh = rem & 3;
        const int cnt = s_cnt[j];
        float m = -3.402823466e38f;
        for (int t = 0; t < cnt; t++) m = fmaxf(m, s_sc[g][s_inc[j][t] * HN + hh]);
        float ex[4], den = 0.f;
        for (int t = 0; t < cnt; t++) {
            ex[t] = __expf(s_sc[g][s_inc[j][t] * HN + hh] - m);
            den += ex[t];
        }
        const float inv = 1.f / den;
        for (int t = 0; t < cnt; t++) s_sc[g][s_inc[j][t] * HN + hh] = ex[t] * inv;
    }
    __syncthreads();

    // ---- weighted gather + bias -> out ----
    float* og = out + (size_t)blockIdx.x * (MROWS * DN);
    for (int idx = tid; idx < MROWS * 64; idx += TPB) {
        const int row = idx >> 6, q = idx & 63;     // q: float4 column
        const int g = row / JN, j = row - g * JN;
        const int hh = q >> 4;
        float4 o = ((const float4*)s_bias)[q];
        const int cnt = s_cnt[j];
        for (int t = 0; t < cnt; t++) {
            const int e = s_inc[j][t];
            const float a = s_sc[g][e * HN + hh];
            const float4 hv = *(const float4*)&hb[(g * JN + s_src[e]) * HSTR + q * 4];
            o.x += a * hv.x; o.y += a * hv.y; o.z += a * hv.z; o.w += a * hv.w;
        }
        *(float4*)&og[(size_t)row * DN + q * 4] = o;
    }
}

extern "C" void kernel_launch(void* const* d_in, const int* in_sizes, int n_in,
                              void* d_out, int out_size) {
    const float* x        = (const float*)d_in[0];
    const float* W        = (const float*)d_in[1];
    const float* att_src  = (const float*)d_in[2];
    const float* att_dst  = (const float*)d_in[3];
    const float* bias     = (const float*)d_in[4];
    const int*   edge_idx = (const int*)d_in[5];
    float* out = (float*)d_out;

    const int E0   = in_sizes[5] / 2;                 // 46
    const int grid = in_sizes[0] / (MROWS * DN);      // 2048

    cudaFuncSetAttribute(gat_mma_kernel, cudaFuncAttributeMaxDynamicSharedMemorySize, DYN_SMEM);
    prep_W<<<64, 256>>>(W);
    gat_mma_kernel<<<grid, TPB, DYN_SMEM>>>(x, att_src, att_dst, bias, edge_idx, out, E0);
}

// round 8
// speedup vs baseline: 1.2951x; 1.2951x over previous
#include <cuda_runtime.h>
#include <cuda_fp16.h>
#include <cstdint>

#define JN    24
#define DN    256
#define HN    4
#define DHC   64
#define GPC   2
#define MROWS 48          // 2 graphs x 24 rows, contiguous in x
#define TPB   256
#define EMAX  80
#define HSTR  260         // padded fp32 row stride for h staging
#define AIMG  24576       // one A image: 48 rows x 512B
#define DYN_SMEM (MROWS * HSTR * 4)   // 49920 >= 2*AIMG = 49152

// W fragment image (fp16): [n-tile 0..31][k-step 0..15][lane][2 regs]
__device__ uint32_t g_Bfrag[32][16][32][2];   // 128 KB

__device__ __forceinline__ uint32_t smem_u32(const void* p) {
    uint32_t a;
    asm("{ .reg .u64 t; cvta.to.shared.u64 t, %1; cvt.u32.u64 %0, t; }" : "=r"(a) : "l"(p));
    return a;
}
__device__ __forceinline__ uint32_t packh(__half a, __half b) {
    return (uint32_t)__half_as_ushort(a) | ((uint32_t)__half_as_ushort(b) << 16);
}

#define LDMATRIX_X4(r0, r1, r2, r3, addr) \
    asm volatile("ldmatrix.sync.aligned.m8n8.x4.shared.b16 {%0,%1,%2,%3}, [%4];" \
        : "=r"(r0), "=r"(r1), "=r"(r2), "=r"(r3) : "r"(addr))

#define MMA_F16(acc, a, b0, b1) \
    asm volatile("mma.sync.aligned.m16n8k16.row.col.f32.f16.f16.f32 " \
        "{%0,%1,%2,%3}, {%4,%5,%6,%7}, {%8,%9}, {%0,%1,%2,%3};" \
        : "+f"((acc)[0]), "+f"((acc)[1]), "+f"((acc)[2]), "+f"((acc)[3]) \
        : "r"((a)[0]), "r"((a)[1]), "r"((a)[2]), "r"((a)[3]), "r"(b0), "r"(b1))

// ---------------- prep: W -> fp16 fragment-linear image ----------------
__global__ void prep_W(const float* __restrict__ W) {
    int idx = blockIdx.x * 256 + threadIdx.x;   // 0..16383 = nt*512 + ks*32 + lane
    int nt = idx >> 9, ks = (idx >> 5) & 15, l = idx & 31;
    int n = nt * 8 + (l >> 2);
#pragma unroll
    for (int r = 0; r < 2; r++) {
        int k = ks * 16 + r * 8 + (l & 3) * 2;
        float v0 = W[(size_t)k * DN + n];
        float v1 = W[(size_t)(k + 1) * DN + n];
        g_Bfrag[nt][ks][l][r] = packh(__float2half(v0), __float2half(v1));
    }
}

// ---------------- main fused kernel ----------------
__global__ void __launch_bounds__(TPB, 2) gat_mma_kernel(
    const float* __restrict__ x,
    const float* __restrict__ att_src_g, const float* __restrict__ att_dst_g,
    const float* __restrict__ bias, const int* __restrict__ edge_index,
    float* __restrict__ out, int E0)
{
    extern __shared__ unsigned char dynraw[];
    __shared__ float s_att[2 * DN];
    __shared__ float s_bias[DN];
    __shared__ float s_as[MROWS * HN], s_ad[MROWS * HN];
    __shared__ float s_sc[GPC][EMAX * HN];
    __shared__ int   s_src[EMAX], s_dst[EMAX];
    __shared__ int   s_inc[JN][4], s_cnt[JN];

    const int tid = threadIdx.x;
    const int w = tid >> 5, l = tid & 31;
    const uint32_t dynb = smem_u32(dynraw);
    const int E = E0 + JN;

    // ---- small tensors ----
    for (int i = tid; i < 2 * DN; i += TPB)
        s_att[i] = (i < DN) ? att_src_g[i] : att_dst_g[i - DN];
    for (int i = tid; i < DN; i += TPB) s_bias[i] = bias[i];
    if (tid < E0) { s_src[tid] = edge_index[tid]; s_dst[tid] = edge_index[E0 + tid]; }
    if (tid < JN) { s_src[E0 + tid] = tid; s_dst[E0 + tid] = tid; }

    // ---- convert x -> A_hi / A_lo fp16 images in SMEM (XOR-swizzled) ----
    {
        const float* xg = x + (size_t)blockIdx.x * (MROWS * DN);
#pragma unroll
        for (int i = 0; i < 6; i++) {
            int task = tid + i * TPB;          // 0..1535
            int r = task >> 5, c = task & 31;  // row, 8-float chunk
            const float4 a = *(const float4*)(xg + (size_t)r * DN + c * 8);
            const float4 b = *(const float4*)(xg + (size_t)r * DN + c * 8 + 4);
            float v[8] = {a.x, a.y, a.z, a.w, b.x, b.y, b.z, b.w};
            uint32_t hi[4], lo[4];
#pragma unroll
            for (int p = 0; p < 4; p++) {
                __half h0 = __float2half(v[2 * p]);
                __half h1 = __float2half(v[2 * p + 1]);
                hi[p] = packh(h0, h1);
                lo[p] = packh(__float2half(v[2 * p]     - __half2float(h0)),
                              __float2half(v[2 * p + 1] - __half2float(h1)));
            }
            uint32_t off = (uint32_t)r * 512u + (uint32_t)((c ^ (r & 7)) << 4);
            *(uint4*)(dynraw + off)        = make_uint4(hi[0], hi[1], hi[2], hi[3]);
            *(uint4*)(dynraw + AIMG + off) = make_uint4(lo[0], lo[1], lo[2], lo[3]);
        }
    }
    __syncthreads();

    // incoming-edge lists (chain graph: cnt <= 3)
    if (tid < JN) {
        int c = 0;
        for (int e = 0; e < E; e++)
            if (s_dst[e] == tid) { if (c < 4) s_inc[tid][c] = e; c++; }
        s_cnt[tid] = c < 4 ? c : 4;
    }

    // ---- GEMM: warp w owns M=48 rows x 32 columns (n-tiles 4w..4w+3) ----
    float acc[3][4][4];
#pragma unroll
    for (int mt = 0; mt < 3; mt++)
#pragma unroll
        for (int nt = 0; nt < 4; nt++)
            acc[mt][nt][0] = acc[mt][nt][1] = acc[mt][nt][2] = acc[mt][nt][3] = 0.f;

    const uint2* bhp = (const uint2*)&g_Bfrag[w * 4][0][l][0];

    uint32_t Bh[2][4][2];
#pragma unroll
    for (int nt = 0; nt < 4; nt++) {
        uint2 vh = __ldg(&bhp[nt * 512]);
        Bh[0][nt][0] = vh.x; Bh[0][nt][1] = vh.y;
    }

    const uint32_t arow = (uint32_t)(l & 15);
    const uint32_t abase = dynb + arow * 512u;

#pragma unroll 2
    for (int ks = 0; ks < 16; ks++) {
        const int cur = ks & 1, nxt = cur ^ 1;
        const int ksn = (ks + 1) & 15;        // wraps; redundant last prefetch is harmless
#pragma unroll
        for (int nt = 0; nt < 4; nt++) {
            uint2 vh = __ldg(&bhp[nt * 512 + ksn * 32]);
            Bh[nxt][nt][0] = vh.x; Bh[nxt][nt][1] = vh.y;
        }
        const uint32_t kc = (uint32_t)(ks * 2 + (l >> 4));
        const uint32_t koff = (kc ^ (arow & 7u)) << 4;

        // hoist all 6 ldmatrix for this k-step, then run 24 MMAs
        uint32_t ah[3][4], al[3][4];
#pragma unroll
        for (int mt = 0; mt < 3; mt++) {
            const uint32_t aoff = abase + (uint32_t)(mt * 16) * 512u + koff;
            LDMATRIX_X4(ah[mt][0], ah[mt][1], ah[mt][2], ah[mt][3], aoff);
            LDMATRIX_X4(al[mt][0], al[mt][1], al[mt][2], al[mt][3], aoff + AIMG);
        }
#pragma unroll
        for (int mt = 0; mt < 3; mt++)
#pragma unroll
            for (int nt = 0; nt < 4; nt++)
                MMA_F16(acc[mt][nt], ah[mt], Bh[cur][nt][0], Bh[cur][nt][1]);
#pragma unroll
        for (int mt = 0; mt < 3; mt++)
#pragma unroll
            for (int nt = 0; nt < 4; nt++)
                MMA_F16(acc[mt][nt], al[mt], Bh[cur][nt][0], Bh[cur][nt][1]);
    }
    __syncthreads();   // all warps done reading A images before h overwrite

    // ---- store h to SMEM (row-major, stride HSTR) ----
    float* hb = (float*)dynraw;
    {
        const int gid = l >> 2, tig = l & 3;
#pragma unroll
        for (int mt = 0; mt < 3; mt++) {
#pragma unroll
            for (int nt = 0; nt < 4; nt++) {
                const int col = w * 32 + nt * 8 + 2 * tig;
                float* p0 = hb + (mt * 16 + gid) * HSTR + col;
                float* p1 = hb + (mt * 16 + gid + 8) * HSTR + col;
                p0[0] = acc[mt][nt][0]; p0[1] = acc[mt][nt][1];
                p1[0] = acc[mt][nt][2]; p1[1] = acc[mt][nt][3];
            }
        }
    }
    __syncthreads();

    // ---- attention dots a_s, a_d for all (row, head) ----
    if (tid < MROWS * HN) {
        const int row = tid >> 2, hh = tid & 3;
        const float* hr = hb + row * HSTR + hh * DHC;
        float as = 0.f, ad = 0.f;
#pragma unroll 8
        for (int d = 0; d < DHC; d++) {
            float v = hr[d];
            as += v * s_att[hh * DHC + d];
            ad += v * s_att[DN + hh * DHC + d];
        }
        s_as[tid] = as; s_ad[tid] = ad;
    }
    __syncthreads();

    // ---- per-edge scores with leaky_relu(0.2) ----
    for (int idx = tid; idx < GPC * E * HN; idx += TPB) {
        const int g = idx / (E * HN), rem = idx - g * (E * HN);
        const int e = rem >> 2, hh = rem & 3;
        float sc = s_as[(g * JN + s_src[e]) * HN + hh] + s_ad[(g * JN + s_dst[e]) * HN + hh];
        s_sc[g][e * HN + hh] = (sc >= 0.f) ? sc : 0.2f * sc;
    }
    __syncthreads();

    // ---- segment softmax: alpha written in place into s_sc ----
    if (tid < GPC * JN * HN) {
        const int g = tid / (JN * HN), rem = tid - g * (JN * HN);
        const int j = rem >> 2, hh = rem & 3;
        const int cnt = s_cnt[j];
        float m = -3.402823466e38f;
        for (int t = 0; t < cnt; t++) m = fmaxf(m, s_sc[g][s_inc[j][t] * HN + hh]);
        float ex[4], den = 0.f;
        for (int t = 0; t < cnt; t++) {
            ex[t] = __expf(s_sc[g][s_inc[j][t] * HN + hh] - m);
            den += ex[t];
        }
        const float inv = 1.f / den;
        for (int t = 0; t < cnt; t++) s_sc[g][s_inc[j][t] * HN + hh] = ex[t] * inv;
    }
    __syncthreads();

    // ---- weighted gather + bias -> out ----
    float* og = out + (size_t)blockIdx.x * (MROWS * DN);
    for (int idx = tid; idx < MROWS * 64; idx += TPB) {
        const int row = idx >> 6, q = idx & 63;     // q: float4 column
        const int g = row / JN, j = row - g * JN;
        const int hh = q >> 4;
        float4 o = ((const float4*)s_bias)[q];
        const int cnt = s_cnt[j];
        for (int t = 0; t < cnt; t++) {
            const int e = s_inc[j][t];
            const float a = s_sc[g][e * HN + hh];
            const float4 hv = *(const float4*)&hb[(g * JN + s_src[e]) * HSTR + q * 4];
            o.x += a * hv.x; o.y += a * hv.y; o.z += a * hv.z; o.w += a * hv.w;
        }
        *(float4*)&og[(size_t)row * DN + q * 4] = o;
    }
}

extern "C" void kernel_launch(void* const* d_in, const int* in_sizes, int n_in,
                              void* d_out, int out_size) {
    const float* x        = (const float*)d_in[0];
    const float* W        = (const float*)d_in[1];
    const float* att_src  = (const float*)d_in[2];
    const float* att_dst  = (const float*)d_in[3];
    const float* bias     = (const float*)d_in[4];
    const int*   edge_idx = (const int*)d_in[5];
    float* out = (float*)d_out;

    const int E0   = in_sizes[5] / 2;                 // 46
    const int grid = in_sizes[0] / (MROWS * DN);      // 2048

    cudaFuncSetAttribute(gat_mma_kernel, cudaFuncAttributeMaxDynamicSharedMemorySize, DYN_SMEM);
    prep_W<<<64, 256>>>(W);
    gat_mma_kernel<<<grid, TPB, DYN_SMEM>>>(x, att_src, att_dst, bias, edge_idx, out, E0);
}

// round 9
// speedup vs baseline: 1.4004x; 1.0813x over previous
#include <cuda_runtime.h>
#include <cuda_fp16.h>
#include <cstdint>

#define JN    24
#define DN    256
#define HN    4
#define DHC   64
#define GPC   2
#define MROWS 48          // 2 graphs x 24 rows, contiguous in x
#define TPB   256
#define EMAX  80
#define HSTR  260         // padded fp32 row stride for h staging
#define DYN_SMEM (MROWS * HSTR * 4)   // 49920 >= A image 24576

// W fragment image (fp16): [n-tile 0..31][k-step 0..15][lane][2 regs]
__device__ uint32_t g_Bfrag[32][16][32][2];   // 128 KB

__device__ __forceinline__ uint32_t smem_u32(const void* p) {
    uint32_t a;
    asm("{ .reg .u64 t; cvta.to.shared.u64 t, %1; cvt.u32.u64 %0, t; }" : "=r"(a) : "l"(p));
    return a;
}
__device__ __forceinline__ uint32_t packh(__half a, __half b) {
    return (uint32_t)__half_as_ushort(a) | ((uint32_t)__half_as_ushort(b) << 16);
}

#define LDMATRIX_X4(r0, r1, r2, r3, addr) \
    asm volatile("ldmatrix.sync.aligned.m8n8.x4.shared.b16 {%0,%1,%2,%3}, [%4];" \
        : "=r"(r0), "=r"(r1), "=r"(r2), "=r"(r3) : "r"(addr))

#define MMA_F16(acc, a, b0, b1) \
    asm volatile("mma.sync.aligned.m16n8k16.row.col.f32.f16.f16.f32 " \
        "{%0,%1,%2,%3}, {%4,%5,%6,%7}, {%8,%9}, {%0,%1,%2,%3};" \
        : "+f"((acc)[0]), "+f"((acc)[1]), "+f"((acc)[2]), "+f"((acc)[3]) \
        : "r"((a)[0]), "r"((a)[1]), "r"((a)[2]), "r"((a)[3]), "r"(b0), "r"(b1))

// ---------------- prep: W -> fp16 fragment-linear image ----------------
__global__ void prep_W(const float* __restrict__ W) {
    int idx = blockIdx.x * 256 + threadIdx.x;   // 0..16383 = nt*512 + ks*32 + lane
    int nt = idx >> 9, ks = (idx >> 5) & 15, l = idx & 31;
    int n = nt * 8 + (l >> 2);
#pragma unroll
    for (int r = 0; r < 2; r++) {
        int k = ks * 16 + r * 8 + (l & 3) * 2;
        float v0 = W[(size_t)k * DN + n];
        float v1 = W[(size_t)(k + 1) * DN + n];
        g_Bfrag[nt][ks][l][r] = packh(__float2half(v0), __float2half(v1));
    }
}

// ---------------- main fused kernel ----------------
__global__ void __launch_bounds__(TPB, 2) gat_mma_kernel(
    const float* __restrict__ x,
    const float* __restrict__ att_src_g, const float* __restrict__ att_dst_g,
    const float* __restrict__ bias, const int* __restrict__ edge_index,
    float* __restrict__ out, int E0)
{
    extern __shared__ unsigned char dynraw[];
    __shared__ float s_att[2 * DN];
    __shared__ float s_bias[DN];
    __shared__ float s_as[MROWS * HN], s_ad[MROWS * HN];
    __shared__ float s_sc[GPC][EMAX * HN];
    __shared__ int   s_src[EMAX], s_dst[EMAX];
    __shared__ int   s_inc[JN][4], s_cnt[JN];

    const int tid = threadIdx.x;
    const int w = tid >> 5, l = tid & 31;
    const uint32_t dynb = smem_u32(dynraw);
    const int E = E0 + JN;

    // ---- small tensors ----
    for (int i = tid; i < 2 * DN; i += TPB)
        s_att[i] = (i < DN) ? att_src_g[i] : att_dst_g[i - DN];
    for (int i = tid; i < DN; i += TPB) s_bias[i] = bias[i];
    if (tid < E0) { s_src[tid] = edge_index[tid]; s_dst[tid] = edge_index[E0 + tid]; }
    if (tid < JN) { s_src[E0 + tid] = tid; s_dst[E0 + tid] = tid; }

    // ---- convert x -> fp16 A image in SMEM (XOR-swizzled) ----
    {
        const float* xg = x + (size_t)blockIdx.x * (MROWS * DN);
#pragma unroll
        for (int i = 0; i < 6; i++) {
            int task = tid + i * TPB;          // 0..1535
            int r = task >> 5, c = task & 31;  // row, 8-float chunk
            const float4 a = *(const float4*)(xg + (size_t)r * DN + c * 8);
            const float4 b = *(const float4*)(xg + (size_t)r * DN + c * 8 + 4);
            uint32_t hi[4];
            hi[0] = packh(__float2half(a.x), __float2half(a.y));
            hi[1] = packh(__float2half(a.z), __float2half(a.w));
            hi[2] = packh(__float2half(b.x), __float2half(b.y));
            hi[3] = packh(__float2half(b.z), __float2half(b.w));
            uint32_t off = (uint32_t)r * 512u + (uint32_t)((c ^ (r & 7)) << 4);
            *(uint4*)(dynraw + off) = make_uint4(hi[0], hi[1], hi[2], hi[3]);
        }
    }
    __syncthreads();

    // incoming-edge lists (chain graph: cnt <= 3)
    if (tid < JN) {
        int c = 0;
        for (int e = 0; e < E; e++)
            if (s_dst[e] == tid) { if (c < 4) s_inc[tid][c] = e; c++; }
        s_cnt[tid] = c < 4 ? c : 4;
    }

    // ---- GEMM: warp w owns M=48 rows x 32 columns (n-tiles 4w..4w+3) ----
    float acc[3][4][4];
#pragma unroll
    for (int mt = 0; mt < 3; mt++)
#pragma unroll
        for (int nt = 0; nt < 4; nt++)
            acc[mt][nt][0] = acc[mt][nt][1] = acc[mt][nt][2] = acc[mt][nt][3] = 0.f;

    const uint2* bhp = (const uint2*)&g_Bfrag[w * 4][0][l][0];

    uint32_t Bh[2][4][2];
#pragma unroll
    for (int nt = 0; nt < 4; nt++) {
        uint2 vh = __ldg(&bhp[nt * 512]);
        Bh[0][nt][0] = vh.x; Bh[0][nt][1] = vh.y;
    }

    const uint32_t arow = (uint32_t)(l & 15);
    const uint32_t abase = dynb + arow * 512u;

#pragma unroll 4
    for (int ks = 0; ks < 16; ks++) {
        const int cur = ks & 1, nxt = cur ^ 1;
        const int ksn = (ks + 1) & 15;        // wraps; redundant last prefetch is harmless
#pragma unroll
        for (int nt = 0; nt < 4; nt++) {
            uint2 vh = __ldg(&bhp[nt * 512 + ksn * 32]);
            Bh[nxt][nt][0] = vh.x; Bh[nxt][nt][1] = vh.y;
        }
        const uint32_t kc = (uint32_t)(ks * 2 + (l >> 4));
        const uint32_t koff = (kc ^ (arow & 7u)) << 4;

        // hoist all 3 ldmatrix for this k-step, then run 12 MMAs
        uint32_t ah[3][4];
#pragma unroll
        for (int mt = 0; mt < 3; mt++) {
            const uint32_t aoff = abase + (uint32_t)(mt * 16) * 512u + koff;
            LDMATRIX_X4(ah[mt][0], ah[mt][1], ah[mt][2], ah[mt][3], aoff);
        }
#pragma unroll
        for (int mt = 0; mt < 3; mt++)
#pragma unroll
            for (int nt = 0; nt < 4; nt++)
                MMA_F16(acc[mt][nt], ah[mt], Bh[cur][nt][0], Bh[cur][nt][1]);
    }
    __syncthreads();   // all warps done reading A image before h overwrite

    // ---- store h to SMEM (row-major, stride HSTR) ----
    float* hb = (float*)dynraw;
    {
        const int gid = l >> 2, tig = l & 3;
#pragma unroll
        for (int mt = 0; mt < 3; mt++) {
#pragma unroll
            for (int nt = 0; nt < 4; nt++) {
                const int col = w * 32 + nt * 8 + 2 * tig;
                float* p0 = hb + (mt * 16 + gid) * HSTR + col;
                float* p1 = hb + (mt * 16 + gid + 8) * HSTR + col;
                p0[0] = acc[mt][nt][0]; p0[1] = acc[mt][nt][1];
                p1[0] = acc[mt][nt][2]; p1[1] = acc[mt][nt][3];
            }
        }
    }
    __syncthreads();

    // ---- attention dots a_s, a_d for all (row, head) ----
    if (tid < MROWS * HN) {
        const int row = tid >> 2, hh = tid & 3;
        const float* hr = hb + row * HSTR + hh * DHC;
        float as = 0.f, ad = 0.f;
#pragma unroll 8
        for (int d = 0; d < DHC; d++) {
            float v = hr[d];
            as += v * s_att[hh * DHC + d];
            ad += v * s_att[DN + hh * DHC + d];
        }
        s_as[tid] = as; s_ad[tid] = ad;
    }
    __syncthreads();

    // ---- per-edge scores with leaky_relu(0.2) ----
    for (int idx = tid; idx < GPC * E * HN; idx += TPB) {
        const int g = idx / (E * HN), rem = idx - g * (E * HN);
        const int e = rem >> 2, hh = rem & 3;
        float sc = s_as[(g * JN + s_src[e]) * HN + hh] + s_ad[(g * JN + s_dst[e]) * HN + hh];
        s_sc[g][e * HN + hh] = (sc >= 0.f) ? sc : 0.2f * sc;
    }
    __syncthreads();

    // ---- segment softmax: alpha written in place into s_sc ----
    if (tid < GPC * JN * HN) {
        const int g = tid / (JN * HN), rem = tid - g * (JN * HN);
        const int j = rem >> 2, hh = rem & 3;
        const int cnt = s_cnt[j];
        float m = -3.402823466e38f;
        for (int t = 0; t < cnt; t++) m = fmaxf(m, s_sc[g][s_inc[j][t] * HN + hh]);
        float ex[4], den = 0.f;
        for (int t = 0; t < cnt; t++) {
            ex[t] = __expf(s_sc[g][s_inc[j][t] * HN + hh] - m);
            den += ex[t];
        }
        const float inv = 1.f / den;
        for (int t = 0; t < cnt; t++) s_sc[g][s_inc[j][t] * HN + hh] = ex[t] * inv;
    }
    __syncthreads();

    // ---- weighted gather + bias -> out ----
    float* og = out + (size_t)blockIdx.x * (MROWS * DN);
    for (int idx = tid; idx < MROWS * 64; idx += TPB) {
        const int row = idx >> 6, q = idx & 63;     // q: float4 column
        const int g = row / JN, j = row - g * JN;
        const int hh = q >> 4;
        float4 o = ((const float4*)s_bias)[q];
        const int cnt = s_cnt[j];
        for (int t = 0; t < cnt; t++) {
            const int e = s_inc[j][t];
            const float a = s_sc[g][e * HN + hh];
            const float4 hv = *(const float4*)&hb[(g * JN + s_src[e]) * HSTR + q * 4];
            o.x += a * hv.x; o.y += a * hv.y; o.z += a * hv.z; o.w += a * hv.w;
        }
        *(float4*)&og[(size_t)row * DN + q * 4] = o;
    }
}

extern "C" void kernel_launch(void* const* d_in, const int* in_sizes, int n_in,
                              void* d_out, int out_size) {
    const float* x        = (const float*)d_in[0];
    const float* W        = (const float*)d_in[1];
    const float* att_src  = (const float*)d_in[2];
    const float* att_dst  = (const float*)d_in[3];
    const float* bias     = (const float*)d_in[4];
    const int*   edge_idx = (const int*)d_in[5];
    float* out = (float*)d_out;

    const int E0   = in_sizes[5] / 2;                 // 46
    const int grid = in_sizes[0] / (MROWS * DN);      // 2048

    cudaFuncSetAttribute(gat_mma_kernel, cudaFuncAttributeMaxDynamicSharedMemorySize, DYN_SMEM);
    prep_W<<<64, 256>>>(W);
    gat_mma_kernel<<<grid, TPB, DYN_SMEM>>>(x, att_src, att_dst, bias, edge_idx, out, E0);
}

// round 10
// speedup vs baseline: 1.4866x; 1.0615x over previous
#include <cuda_runtime.h>
#include <cuda_fp16.h>
#include <cstdint>

#define JN    24
#define DN    256
#define HN    4
#define DHC   64
#define TPB   256
#define EMAX  80
#define HSTR2 264         // padded half row stride for h staging
#define DYN_SMEM 16384    // A image 32x512B; h (24*264*2=12672B) reuses it

// W fragment image (fp16): [n-tile 0..31][k-step 0..15][lane][2 regs]
__device__ uint32_t g_Bfrag[32][16][32][2];   // 128 KB

__device__ __forceinline__ uint32_t smem_u32(const void* p) {
    uint32_t a;
    asm("{ .reg .u64 t; cvta.to.shared.u64 t, %1; cvt.u32.u64 %0, t; }" : "=r"(a) : "l"(p));
    return a;
}
__device__ __forceinline__ uint32_t packh(__half a, __half b) {
    return (uint32_t)__half_as_ushort(a) | ((uint32_t)__half_as_ushort(b) << 16);
}

#define LDMATRIX_X4(r0, r1, r2, r3, addr) \
    asm volatile("ldmatrix.sync.aligned.m8n8.x4.shared.b16 {%0,%1,%2,%3}, [%4];" \
        : "=r"(r0), "=r"(r1), "=r"(r2), "=r"(r3) : "r"(addr))

#define MMA_F16(acc, a, b0, b1) \
    asm volatile("mma.sync.aligned.m16n8k16.row.col.f32.f16.f16.f32 " \
        "{%0,%1,%2,%3}, {%4,%5,%6,%7}, {%8,%9}, {%0,%1,%2,%3};" \
        : "+f"((acc)[0]), "+f"((acc)[1]), "+f"((acc)[2]), "+f"((acc)[3]) \
        : "r"((a)[0]), "r"((a)[1]), "r"((a)[2]), "r"((a)[3]), "r"(b0), "r"(b1))

// ---------------- prep: W -> fp16 fragment-linear image ----------------
__global__ void prep_W(const float* __restrict__ W) {
    int idx = blockIdx.x * 256 + threadIdx.x;   // 0..16383 = nt*512 + ks*32 + lane
    int nt = idx >> 9, ks = (idx >> 5) & 15, l = idx & 31;
    int n = nt * 8 + (l >> 2);
#pragma unroll
    for (int r = 0; r < 2; r++) {
        int k = ks * 16 + r * 8 + (l & 3) * 2;
        float v0 = W[(size_t)k * DN + n];
        float v1 = W[(size_t)(k + 1) * DN + n];
        g_Bfrag[nt][ks][l][r] = packh(__float2half(v0), __float2half(v1));
    }
}

// ---------------- main fused kernel: 1 graph per CTA ----------------
__global__ void __launch_bounds__(TPB, 4) gat_mma_kernel(
    const float* __restrict__ x,
    const float* __restrict__ att_src_g, const float* __restrict__ att_dst_g,
    const float* __restrict__ bias, const int* __restrict__ edge_index,
    float* __restrict__ out, int E0)
{
    extern __shared__ unsigned char dynraw[];
    __shared__ float s_att[2 * DN];
    __shared__ float s_bias[DN];
    __shared__ float s_as[JN * HN], s_ad[JN * HN];
    __shared__ float s_sc[EMAX * HN];
    __shared__ int   s_src[EMAX], s_dst[EMAX];
    __shared__ int   s_inc[JN][4], s_cnt[JN];

    const int tid = threadIdx.x;
    const int w = tid >> 5, l = tid & 31;
    const uint32_t dynb = smem_u32(dynraw);
    const int E = E0 + JN;

    // ---- small tensors ----
    for (int i = tid; i < 2 * DN; i += TPB)
        s_att[i] = (i < DN) ? att_src_g[i] : att_dst_g[i - DN];
    for (int i = tid; i < DN; i += TPB) s_bias[i] = bias[i];
    if (tid < E0) { s_src[tid] = edge_index[tid]; s_dst[tid] = edge_index[E0 + tid]; }
    if (tid < JN) { s_src[E0 + tid] = tid; s_dst[E0 + tid] = tid; }

    // ---- convert x -> fp16 A image in SMEM (XOR-swizzled), rows 24..31 zero ----
    {
        const float* xg = x + (size_t)blockIdx.x * (JN * DN);
        // zero the pad rows (rows 24..31): 8 rows x 512B = 4096B
        for (int i = tid; i < 256; i += TPB)
            *(uint4*)(dynraw + 24 * 512 + i * 16) = make_uint4(0, 0, 0, 0);
#pragma unroll
        for (int i = 0; i < 3; i++) {
            int task = tid + i * TPB;          // 0..767 : row (0..23), 8-float chunk
            int r = task >> 5, c = task & 31;
            const float4 a = *(const float4*)(xg + (size_t)r * DN + c * 8);
            const float4 b = *(const float4*)(xg + (size_t)r * DN + c * 8 + 4);
            uint32_t hi[4];
            hi[0] = packh(__float2half(a.x), __float2half(a.y));
            hi[1] = packh(__float2half(a.z), __float2half(a.w));
            hi[2] = packh(__float2half(b.x), __float2half(b.y));
            hi[3] = packh(__float2half(b.z), __float2half(b.w));
            uint32_t off = (uint32_t)r * 512u + (uint32_t)((c ^ (r & 7)) << 4);
            *(uint4*)(dynraw + off) = make_uint4(hi[0], hi[1], hi[2], hi[3]);
        }
    }
    __syncthreads();

    // incoming-edge lists (chain graph: cnt <= 3)
    if (tid < JN) {
        int c = 0;
        for (int e = 0; e < E; e++)
            if (s_dst[e] == tid) { if (c < 4) s_inc[tid][c] = e; c++; }
        s_cnt[tid] = c < 4 ? c : 4;
    }

    // ---- GEMM: warp w owns M=32 (2 m-tiles) x 32 columns (n-tiles 4w..4w+3) ----
    float acc[2][4][4];
#pragma unroll
    for (int mt = 0; mt < 2; mt++)
#pragma unroll
        for (int nt = 0; nt < 4; nt++)
            acc[mt][nt][0] = acc[mt][nt][1] = acc[mt][nt][2] = acc[mt][nt][3] = 0.f;

    const uint2* bhp = (const uint2*)&g_Bfrag[w * 4][0][l][0];
    const uint32_t arow = (uint32_t)(l & 15);
    const uint32_t abase = dynb + arow * 512u;

#pragma unroll 4
    for (int ks = 0; ks < 16; ks++) {
        uint32_t Bh[4][2];
#pragma unroll
        for (int nt = 0; nt < 4; nt++) {
            uint2 vh = __ldg(&bhp[nt * 512 + ks * 32]);
            Bh[nt][0] = vh.x; Bh[nt][1] = vh.y;
        }
        const uint32_t kc = (uint32_t)(ks * 2 + (l >> 4));
        const uint32_t koff = (kc ^ (arow & 7u)) << 4;
        uint32_t ah[2][4];
#pragma unroll
        for (int mt = 0; mt < 2; mt++)
            LDMATRIX_X4(ah[mt][0], ah[mt][1], ah[mt][2], ah[mt][3],
                        abase + (uint32_t)(mt * 16) * 512u + koff);
#pragma unroll
        for (int mt = 0; mt < 2; mt++)
#pragma unroll
            for (int nt = 0; nt < 4; nt++)
                MMA_F16(acc[mt][nt], ah[mt], Bh[nt][0], Bh[nt][1]);
    }
    __syncthreads();   // all warps done reading A image before h overwrite

    // ---- store h to SMEM as fp16 (row stride HSTR2 halves) ----
    __half* hb = (__half*)dynraw;
    {
        const int gid = l >> 2, tig = l & 3;
#pragma unroll
        for (int mt = 0; mt < 2; mt++) {
            const int r0 = mt * 16 + gid;       // rows r0, r0+8
#pragma unroll
            for (int nt = 0; nt < 4; nt++) {
                const int col = w * 32 + nt * 8 + 2 * tig;
                if (r0 < JN)
                    *(uint32_t*)&hb[r0 * HSTR2 + col] =
                        packh(__float2half(acc[mt][nt][0]), __float2half(acc[mt][nt][1]));
                if (r0 + 8 < JN)
                    *(uint32_t*)&hb[(r0 + 8) * HSTR2 + col] =
                        packh(__float2half(acc[mt][nt][2]), __float2half(acc[mt][nt][3]));
            }
        }
    }
    __syncthreads();

    // ---- attention dots a_s, a_d for all (row, head) ----
    if (tid < JN * HN) {
        const int row = tid >> 2, hh = tid & 3;
        const __half2* hr = (const __half2*)&hb[row * HSTR2 + hh * DHC];
        float as = 0.f, ad = 0.f;
#pragma unroll 8
        for (int d = 0; d < DHC / 2; d++) {
            float2 v = __half22float2(hr[d]);
            as += v.x * s_att[hh * DHC + 2 * d]     + v.y * s_att[hh * DHC + 2 * d + 1];
            ad += v.x * s_att[DN + hh * DHC + 2 * d] + v.y * s_att[DN + hh * DHC + 2 * d + 1];
        }
        s_as[tid] = as; s_ad[tid] = ad;
    }
    __syncthreads();

    // ---- per-edge scores with leaky_relu(0.2) ----
    for (int idx = tid; idx < E * HN; idx += TPB) {
        const int e = idx >> 2, hh = idx & 3;
        float sc = s_as[s_src[e] * HN + hh] + s_ad[s_dst[e] * HN + hh];
        s_sc[e * HN + hh] = (sc >= 0.f) ? sc : 0.2f * sc;
    }
    __syncthreads();

    // ---- segment softmax: alpha written in place into s_sc ----
    if (tid < JN * HN) {
        const int j = tid >> 2, hh = tid & 3;
        const int cnt = s_cnt[j];
        float m = -3.402823466e38f;
        for (int t = 0; t < cnt; t++) m = fmaxf(m, s_sc[s_inc[j][t] * HN + hh]);
        float ex[4], den = 0.f;
        for (int t = 0; t < cnt; t++) {
            ex[t] = __expf(s_sc[s_inc[j][t] * HN + hh] - m);
            den += ex[t];
        }
        const float inv = 1.f / den;
        for (int t = 0; t < cnt; t++) s_sc[s_inc[j][t] * HN + hh] = ex[t] * inv;
    }
    __syncthreads();

    // ---- weighted gather + bias -> out ----
    float* og = out + (size_t)blockIdx.x * (JN * DN);
    for (int idx = tid; idx < JN * 64; idx += TPB) {
        const int j = idx >> 6, q = idx & 63;       // q: float4 column group
        const int hh = q >> 4;
        float4 o = ((const float4*)s_bias)[q];
        const int cnt = s_cnt[j];
        for (int t = 0; t < cnt; t++) {
            const int e = s_inc[j][t];
            const float a = s_sc[e * HN + hh];
            const uint2 hv = *(const uint2*)&hb[s_src[e] * HSTR2 + q * 4];
            float2 v0 = __half22float2(*(const __half2*)&hv.x);
            float2 v1 = __half22float2(*(const __half2*)&hv.y);
            o.x += a * v0.x; o.y += a * v0.y; o.z += a * v1.x; o.w += a * v1.y;
        }
        *(float4*)&og[(size_t)j * DN + q * 4] = o;
    }
}

extern "C" void kernel_launch(void* const* d_in, const int* in_sizes, int n_in,
                              void* d_out, int out_size) {
    const float* x        = (const float*)d_in[0];
    const float* W        = (const float*)d_in[1];
    const float* att_src  = (const float*)d_in[2];
    const float* att_dst  = (const float*)d_in[3];
    const float* bias     = (const float*)d_in[4];
    const int*   edge_idx = (const int*)d_in[5];
    float* out = (float*)d_out;

    const int E0   = in_sizes[5] / 2;            // 46
    const int grid = in_sizes[0] / (JN * DN);    // 4096

    cudaFuncSetAttribute(gat_mma_kernel, cudaFuncAttributeMaxDynamicSharedMemorySize, DYN_SMEM);
    prep_W<<<64, 256>>>(W);
    gat_mma_kernel<<<grid, TPB, DYN_SMEM>>>(x, att_src, att_dst, bias, edge_idx, out, E0);
}

// round 11
// speedup vs baseline: 1.6133x; 1.0852x over previous
#include <cuda_runtime.h>
#include <cuda_fp16.h>
#include <cstdint>

#define JN    24
#define DN    256
#define HN    4
#define DHC   64
#define TPB   256
#define EMAX  80
#define HSTR  260                 // padded fp32 row stride for h staging
#define DYN_SMEM (32 * HSTR * 4)  // 33280 B: A image (16KB) then h fp32 (32 rows)

// W fragment image (fp16): [nt-pair 0..15][k-step 0..15][lane][4 regs]
__device__ uint32_t g_Bfrag[16][16][32][4];   // 128 KB

__device__ __forceinline__ uint32_t smem_u32(const void* p) {
    uint32_t a;
    asm("{ .reg .u64 t; cvta.to.shared.u64 t, %1; cvt.u32.u64 %0, t; }" : "=r"(a) : "l"(p));
    return a;
}
__device__ __forceinline__ uint32_t packh(__half a, __half b) {
    return (uint32_t)__half_as_ushort(a) | ((uint32_t)__half_as_ushort(b) << 16);
}

#define LDMATRIX_X4(r0, r1, r2, r3, addr) \
    asm volatile("ldmatrix.sync.aligned.m8n8.x4.shared.b16 {%0,%1,%2,%3}, [%4];" \
        : "=r"(r0), "=r"(r1), "=r"(r2), "=r"(r3) : "r"(addr))

#define MMA_F16(acc, a, b0, b1) \
    asm volatile("mma.sync.aligned.m16n8k16.row.col.f32.f16.f16.f32 " \
        "{%0,%1,%2,%3}, {%4,%5,%6,%7}, {%8,%9}, {%0,%1,%2,%3};" \
        : "+f"((acc)[0]), "+f"((acc)[1]), "+f"((acc)[2]), "+f"((acc)[3]) \
        : "r"((a)[0]), "r"((a)[1]), "r"((a)[2]), "r"((a)[3]), "r"(b0), "r"(b1))

// ---------------- prep: W -> fp16 fragment-linear image (nt-paired) ----------------
__global__ void prep_W(const float* __restrict__ W) {
    int idx = blockIdx.x * 256 + threadIdx.x;   // 0..8191 = pr*512 + ks*32 + lane
    if (idx >= 8192) return;
    int pr = idx >> 9, ks = (idx >> 5) & 15, l = idx & 31;
#pragma unroll
    for (int r = 0; r < 4; r++) {
        int nt = pr * 2 + (r >> 1);
        int rr = r & 1;
        int k = ks * 16 + rr * 8 + (l & 3) * 2;
        int n = nt * 8 + (l >> 2);
        float v0 = W[(size_t)k * DN + n];
        float v1 = W[(size_t)(k + 1) * DN + n];
        g_Bfrag[pr][ks][l][r] = packh(__float2half(v0), __float2half(v1));
    }
}

// ---------------- main fused kernel: 1 graph per CTA ----------------
__global__ void __launch_bounds__(TPB, 4) gat_mma_kernel(
    const float* __restrict__ x,
    const float* __restrict__ att_src_g, const float* __restrict__ att_dst_g,
    const float* __restrict__ bias, const int* __restrict__ edge_index,
    float* __restrict__ out, int E0)
{
    extern __shared__ unsigned char dynraw[];
    __shared__ float s_att[2 * DN];
    __shared__ float s_bias[DN];
    __shared__ float s_as[JN * HN], s_ad[JN * HN];
    __shared__ float s_sc[EMAX * HN];
    __shared__ int   s_src[EMAX], s_dst[EMAX];
    __shared__ int   s_inc[JN][4], s_cnt[JN];

    const int tid = threadIdx.x;
    const int w = tid >> 5, l = tid & 31;
    const int gid = l >> 2, tig = l & 3;
    const uint32_t dynb = smem_u32(dynraw);
    const int E = E0 + JN;

    // ---- small tensors + zero accum targets ----
    for (int i = tid; i < 2 * DN; i += TPB)
        s_att[i] = (i < DN) ? att_src_g[i] : att_dst_g[i - DN];
    for (int i = tid; i < DN; i += TPB) s_bias[i] = bias[i];
    if (tid < JN * HN) { s_as[tid] = 0.f; s_ad[tid] = 0.f; }
    if (tid < E0) { s_src[tid] = edge_index[tid]; s_dst[tid] = edge_index[E0 + tid]; }
    if (tid < JN) { s_src[E0 + tid] = tid; s_dst[E0 + tid] = tid; }

    // ---- convert x -> fp16 A image in SMEM (XOR-swizzled), rows 24..31 zero ----
    {
        const float* xg = x + (size_t)blockIdx.x * (JN * DN);
        for (int i = tid; i < 256; i += TPB)
            *(uint4*)(dynraw + 24 * 512 + i * 16) = make_uint4(0, 0, 0, 0);
#pragma unroll
        for (int i = 0; i < 3; i++) {
            int task = tid + i * TPB;          // 0..767 : row (0..23), 8-float chunk
            int r = task >> 5, c = task & 31;
            const float4 a = *(const float4*)(xg + (size_t)r * DN + c * 8);
            const float4 b = *(const float4*)(xg + (size_t)r * DN + c * 8 + 4);
            uint32_t hi[4];
            hi[0] = packh(__float2half(a.x), __float2half(a.y));
            hi[1] = packh(__float2half(a.z), __float2half(a.w));
            hi[2] = packh(__float2half(b.x), __float2half(b.y));
            hi[3] = packh(__float2half(b.z), __float2half(b.w));
            uint32_t off = (uint32_t)r * 512u + (uint32_t)((c ^ (r & 7)) << 4);
            *(uint4*)(dynraw + off) = make_uint4(hi[0], hi[1], hi[2], hi[3]);
        }
    }
    __syncthreads();

    // incoming-edge lists (chain graph: cnt <= 3)
    if (tid < JN) {
        int c = 0;
        for (int e = 0; e < E; e++)
            if (s_dst[e] == tid) { if (c < 4) s_inc[tid][c] = e; c++; }
        s_cnt[tid] = c < 4 ? c : 4;
    }

    // ---- GEMM: warp w owns M=32 (2 m-tiles) x 32 columns (n-tiles 4w..4w+3) ----
    float acc[2][4][4];
#pragma unroll
    for (int mt = 0; mt < 2; mt++)
#pragma unroll
        for (int nt = 0; nt < 4; nt++)
            acc[mt][nt][0] = acc[mt][nt][1] = acc[mt][nt][2] = acc[mt][nt][3] = 0.f;

    const uint4* bp = (const uint4*)&g_Bfrag[w * 2][0][l][0];
    const uint32_t arow = (uint32_t)(l & 15);
    const uint32_t abase = dynb + arow * 512u;

#pragma unroll 4
    for (int ks = 0; ks < 16; ks++) {
        const uint4 b0 = __ldg(bp + ks * 32);          // nt0, nt1
        const uint4 b1 = __ldg(bp + 512 + ks * 32);    // nt2, nt3
        const uint32_t kc = (uint32_t)(ks * 2 + (l >> 4));
        const uint32_t koff = (kc ^ (arow & 7u)) << 4;
        uint32_t ah[2][4];
#pragma unroll
        for (int mt = 0; mt < 2; mt++)
            LDMATRIX_X4(ah[mt][0], ah[mt][1], ah[mt][2], ah[mt][3],
                        abase + (uint32_t)(mt * 16) * 512u + koff);
#pragma unroll
        for (int mt = 0; mt < 2; mt++) {
            MMA_F16(acc[mt][0], ah[mt], b0.x, b0.y);
            MMA_F16(acc[mt][1], ah[mt], b0.z, b0.w);
            MMA_F16(acc[mt][2], ah[mt], b1.x, b1.y);
            MMA_F16(acc[mt][3], ah[mt], b1.z, b1.w);
        }
    }
    __syncthreads();   // all warps done reading A image before h overwrite

    // ---- store h fp32 to SMEM (rows incl. pad; stride HSTR) ----
    float* hb = (float*)dynraw;
    {
#pragma unroll
        for (int mt = 0; mt < 2; mt++) {
#pragma unroll
            for (int nt = 0; nt < 4; nt++) {
                const int col = w * 32 + nt * 8 + 2 * tig;
                *(float2*)&hb[(mt * 16 + gid) * HSTR + col] =
                    make_float2(acc[mt][nt][0], acc[mt][nt][1]);
                *(float2*)&hb[(mt * 16 + gid + 8) * HSTR + col] =
                    make_float2(acc[mt][nt][2], acc[mt][nt][3]);
            }
        }
    }

    // ---- attention dots from accumulators: per-lane partials + butterfly + atomics ----
    {
        const int head = w >> 1;
        const int cb = (w & 1) * 32 + 2 * tig;
        float2 av[4], bv[4];
#pragma unroll
        for (int nt = 0; nt < 4; nt++) {
            av[nt] = *(const float2*)&s_att[head * DHC + cb + nt * 8];
            bv[nt] = *(const float2*)&s_att[DN + head * DHC + cb + nt * 8];
        }
        float asl[4], adl[4];
#pragma unroll
        for (int s = 0; s < 4; s++) {
            const int mt = s >> 1, c0 = (s & 1) * 2;
            float sa = 0.f, sd = 0.f;
#pragma unroll
            for (int nt = 0; nt < 4; nt++) {
                sa += acc[mt][nt][c0] * av[nt].x + acc[mt][nt][c0 + 1] * av[nt].y;
                sd += acc[mt][nt][c0] * bv[nt].x + acc[mt][nt][c0 + 1] * bv[nt].y;
            }
            asl[s] = sa; adl[s] = sd;
        }
#pragma unroll
        for (int s = 0; s < 4; s++) {
            asl[s] += __shfl_xor_sync(0xffffffffu, asl[s], 1);
            asl[s] += __shfl_xor_sync(0xffffffffu, asl[s], 2);
            adl[s] += __shfl_xor_sync(0xffffffffu, adl[s], 1);
            adl[s] += __shfl_xor_sync(0xffffffffu, adl[s], 2);
        }
        if (tig == 0) {
#pragma unroll
            for (int s = 0; s < 4; s++) {
                const int row = gid + 8 * s;   // s0:gid s1:gid+8 s2:gid+16 s3:gid+24
                if (row < JN) {
                    atomicAdd(&s_as[row * HN + head], asl[s]);
                    atomicAdd(&s_ad[row * HN + head], adl[s]);
                }
            }
        }
    }
    __syncthreads();

    // ---- per-edge scores with leaky_relu(0.2) ----
    for (int idx = tid; idx < E * HN; idx += TPB) {
        const int e = idx >> 2, hh = idx & 3;
        float sc = s_as[s_src[e] * HN + hh] + s_ad[s_dst[e] * HN + hh];
        s_sc[e * HN + hh] = (sc >= 0.f) ? sc : 0.2f * sc;
    }
    __syncthreads();

    // ---- segment softmax: alpha written in place into s_sc ----
    if (tid < JN * HN) {
        const int j = tid >> 2, hh = tid & 3;
        const int cnt = s_cnt[j];
        float m = -3.402823466e38f;
        for (int t = 0; t < cnt; t++) m = fmaxf(m, s_sc[s_inc[j][t] * HN + hh]);
        float ex[4], den = 0.f;
        for (int t = 0; t < cnt; t++) {
            ex[t] = __expf(s_sc[s_inc[j][t] * HN + hh] - m);
            den += ex[t];
        }
        const float inv = 1.f / den;
        for (int t = 0; t < cnt; t++) s_sc[s_inc[j][t] * HN + hh] = ex[t] * inv;
    }
    __syncthreads();

    // ---- weighted gather + bias -> out ----
    float* og = out + (size_t)blockIdx.x * (JN * DN);
    for (int idx = tid; idx < JN * 64; idx += TPB) {
        const int j = idx >> 6, q = idx & 63;       // q: float4 column group
        const int hh = q >> 4;
        float4 o = ((const float4*)s_bias)[q];
        const int cnt = s_cnt[j];
        for (int t = 0; t < cnt; t++) {
            const int e = s_inc[j][t];
            const float a = s_sc[e * HN + hh];
            const float4 hv = *(const float4*)&hb[s_src[e] * HSTR + q * 4];
            o.x += a * hv.x; o.y += a * hv.y; o.z += a * hv.z; o.w += a * hv.w;
        }
        *(float4*)&og[(size_t)j * DN + q * 4] = o;
    }
}

extern "C" void kernel_launch(void* const* d_in, const int* in_sizes, int n_in,
                              void* d_out, int out_size) {
    const float* x        = (const float*)d_in[0];
    const float* W        = (const float*)d_in[1];
    const float* att_src  = (const float*)d_in[2];
    const float* att_dst  = (const float*)d_in[3];
    const float* bias     = (const float*)d_in[4];
    const int*   edge_idx = (const int*)d_in[5];
    float* out = (float*)d_out;

    const int E0   = in_sizes[5] / 2;            // 46
    const int grid = in_sizes[0] / (JN * DN);    // 4096

    cudaFuncSetAttribute(gat_mma_kernel, cudaFuncAttributeMaxDynamicSharedMemorySize, DYN_SMEM);
    prep_W<<<32, 256>>>(W);
    gat_mma_kernel<<<grid, TPB, DYN_SMEM>>>(x, att_src, att_dst, bias, edge_idx, out, E0);
}

// round 12
// speedup vs baseline: 1.6435x; 1.0187x over previous
#include <cuda_runtime.h>
#include <cuda_fp16.h>
#include <cstdint>

#define JN    24
#define DN    256
#define HN    4
#define DHC   64
#define TPB   256
#define EMAX  80
#define HSTR  260                 // padded fp32 row stride for h staging
#define DYN_SMEM (32 * HSTR * 4)  // 33280 B: A image (16KB) then h fp32 (32 rows)

// W fragment image (fp16): [nt-pair 0..15][k-step 0..15][lane][4 regs]
__device__ uint32_t g_Bfrag[16][16][32][4];   // 128 KB

__device__ __forceinline__ uint32_t smem_u32(const void* p) {
    uint32_t a;
    asm("{ .reg .u64 t; cvta.to.shared.u64 t, %1; cvt.u32.u64 %0, t; }" : "=r"(a) : "l"(p));
    return a;
}
__device__ __forceinline__ uint32_t packh(__half a, __half b) {
    return (uint32_t)__half_as_ushort(a) | ((uint32_t)__half_as_ushort(b) << 16);
}

#define LDMATRIX_X4(r0, r1, r2, r3, addr) \
    asm volatile("ldmatrix.sync.aligned.m8n8.x4.shared.b16 {%0,%1,%2,%3}, [%4];" \
        : "=r"(r0), "=r"(r1), "=r"(r2), "=r"(r3) : "r"(addr))

#define MMA_F16(acc, a, b0, b1) \
    asm volatile("mma.sync.aligned.m16n8k16.row.col.f32.f16.f16.f32 " \
        "{%0,%1,%2,%3}, {%4,%5,%6,%7}, {%8,%9}, {%0,%1,%2,%3};" \
        : "+f"((acc)[0]), "+f"((acc)[1]), "+f"((acc)[2]), "+f"((acc)[3]) \
        : "r"((a)[0]), "r"((a)[1]), "r"((a)[2]), "r"((a)[3]), "r"(b0), "r"(b1))

// ---------------- prep: W -> fp16 fragment-linear image (nt-paired) ----------------
__global__ void prep_W(const float* __restrict__ W) {
    int idx = blockIdx.x * 256 + threadIdx.x;   // 0..8191 = pr*512 + ks*32 + lane
    if (idx >= 8192) return;
    int pr = idx >> 9, ks = (idx >> 5) & 15, l = idx & 31;
#pragma unroll
    for (int r = 0; r < 4; r++) {
        int nt = pr * 2 + (r >> 1);
        int rr = r & 1;
        int k = ks * 16 + rr * 8 + (l & 3) * 2;
        int n = nt * 8 + (l >> 2);
        float v0 = W[(size_t)k * DN + n];
        float v1 = W[(size_t)(k + 1) * DN + n];
        g_Bfrag[pr][ks][l][r] = packh(__float2half(v0), __float2half(v1));
    }
}

// ---------------- main fused kernel: 1 graph per CTA, 2m x 4n warp grid ----------------
__global__ void __launch_bounds__(TPB, 4) gat_mma_kernel(
    const float* __restrict__ x,
    const float* __restrict__ att_src_g, const float* __restrict__ att_dst_g,
    const float* __restrict__ bias, const int* __restrict__ edge_index,
    float* __restrict__ out, int E0)
{
    extern __shared__ unsigned char dynraw[];
    __shared__ float s_att[2 * DN];
    __shared__ float s_bias[DN];
    __shared__ float s_as[JN * HN], s_ad[JN * HN];
    __shared__ float s_sc[EMAX * HN];
    __shared__ int   s_src[EMAX], s_dst[EMAX];
    __shared__ int   s_inc[JN][4], s_cnt[JN];

    const int tid = threadIdx.x;
    const int w = tid >> 5, l = tid & 31;
    const int gid = l >> 2, tig = l & 3;
    const int head = w >> 1, mt = w & 1;    // warp = (m-tile, head)
    const uint32_t dynb = smem_u32(dynraw);
    const int E = E0 + JN;

    // ---- small tensors ----
    for (int i = tid; i < 2 * DN; i += TPB)
        s_att[i] = (i < DN) ? att_src_g[i] : att_dst_g[i - DN];
    for (int i = tid; i < DN; i += TPB) s_bias[i] = bias[i];
    if (tid < E0) { s_src[tid] = edge_index[tid]; s_dst[tid] = edge_index[E0 + tid]; }
    if (tid < JN) { s_src[E0 + tid] = tid; s_dst[E0 + tid] = tid; }

    // ---- convert x -> fp16 A image in SMEM (XOR-swizzled), rows 24..31 zero ----
    {
        const float* xg = x + (size_t)blockIdx.x * (JN * DN);
        for (int i = tid; i < 256; i += TPB)
            *(uint4*)(dynraw + 24 * 512 + i * 16) = make_uint4(0, 0, 0, 0);
#pragma unroll
        for (int i = 0; i < 3; i++) {
            int task = tid + i * TPB;          // 0..767 : row (0..23), 8-float chunk
            int r = task >> 5, c = task & 31;
            const float4 a = *(const float4*)(xg + (size_t)r * DN + c * 8);
            const float4 b = *(const float4*)(xg + (size_t)r * DN + c * 8 + 4);
            uint32_t hi[4];
            hi[0] = packh(__float2half(a.x), __float2half(a.y));
            hi[1] = packh(__float2half(a.z), __float2half(a.w));
            hi[2] = packh(__float2half(b.x), __float2half(b.y));
            hi[3] = packh(__float2half(b.z), __float2half(b.w));
            uint32_t off = (uint32_t)r * 512u + (uint32_t)((c ^ (r & 7)) << 4);
            *(uint4*)(dynraw + off) = make_uint4(hi[0], hi[1], hi[2], hi[3]);
        }
    }
    __syncthreads();

    // incoming-edge lists (chain graph: cnt <= 3)
    if (tid < JN) {
        int c = 0;
        for (int e = 0; e < E; e++)
            if (s_dst[e] == tid) { if (c < 4) s_inc[tid][c] = e; c++; }
        s_cnt[tid] = c < 4 ? c : 4;
    }

    // ---- GEMM: warp owns 16 rows (m-tile mt) x 64 cols (head) ----
    float acc[8][4];
#pragma unroll
    for (int nt = 0; nt < 8; nt++)
        acc[nt][0] = acc[nt][1] = acc[nt][2] = acc[nt][3] = 0.f;

    const uint4* bp = (const uint4*)&g_Bfrag[head * 4][0][l][0];
    const uint32_t arow = (uint32_t)(l & 15);
    const uint32_t abase = dynb + ((uint32_t)(mt * 16) + arow) * 512u;

#pragma unroll 4
    for (int ks = 0; ks < 16; ks++) {
        const uint32_t kc = (uint32_t)(ks * 2 + (l >> 4));
        const uint32_t koff = (kc ^ (arow & 7u)) << 4;
        uint32_t ah[4];
        LDMATRIX_X4(ah[0], ah[1], ah[2], ah[3], abase + koff);
        const uint4 b0 = __ldg(bp + 0 * 512 + ks * 32);
        const uint4 b1 = __ldg(bp + 1 * 512 + ks * 32);
        MMA_F16(acc[0], ah, b0.x, b0.y); MMA_F16(acc[1], ah, b0.z, b0.w);
        MMA_F16(acc[2], ah, b1.x, b1.y); MMA_F16(acc[3], ah, b1.z, b1.w);
        const uint4 b2 = __ldg(bp + 2 * 512 + ks * 32);
        const uint4 b3 = __ldg(bp + 3 * 512 + ks * 32);
        MMA_F16(acc[4], ah, b2.x, b2.y); MMA_F16(acc[5], ah, b2.z, b2.w);
        MMA_F16(acc[6], ah, b3.x, b3.y); MMA_F16(acc[7], ah, b3.z, b3.w);
    }
    __syncthreads();   // all warps done reading A image before h overwrite

    // ---- store h fp32 to SMEM (incl. pad rows; stride HSTR) ----
    float* hb = (float*)dynraw;
    {
#pragma unroll
        for (int nt = 0; nt < 8; nt++) {
            const int col = head * DHC + nt * 8 + 2 * tig;
            *(float2*)&hb[(mt * 16 + gid) * HSTR + col] =
                make_float2(acc[nt][0], acc[nt][1]);
            *(float2*)&hb[(mt * 16 + gid + 8) * HSTR + col] =
                make_float2(acc[nt][2], acc[nt][3]);
        }
    }

    // ---- attention dots from accumulators: warp-local butterfly, plain stores ----
    {
        float sa0 = 0.f, sd0 = 0.f, sa1 = 0.f, sd1 = 0.f;
#pragma unroll
        for (int nt = 0; nt < 8; nt++) {
            const float2 av = *(const float2*)&s_att[head * DHC + nt * 8 + 2 * tig];
            const float2 bv = *(const float2*)&s_att[DN + head * DHC + nt * 8 + 2 * tig];
            sa0 += acc[nt][0] * av.x + acc[nt][1] * av.y;
            sd0 += acc[nt][0] * bv.x + acc[nt][1] * bv.y;
            sa1 += acc[nt][2] * av.x + acc[nt][3] * av.y;
            sd1 += acc[nt][2] * bv.x + acc[nt][3] * bv.y;
        }
        sa0 += __shfl_xor_sync(0xffffffffu, sa0, 1); sa0 += __shfl_xor_sync(0xffffffffu, sa0, 2);
        sd0 += __shfl_xor_sync(0xffffffffu, sd0, 1); sd0 += __shfl_xor_sync(0xffffffffu, sd0, 2);
        sa1 += __shfl_xor_sync(0xffffffffu, sa1, 1); sa1 += __shfl_xor_sync(0xffffffffu, sa1, 2);
        sd1 += __shfl_xor_sync(0xffffffffu, sd1, 1); sd1 += __shfl_xor_sync(0xffffffffu, sd1, 2);
        if (tig == 0) {
            const int r0 = mt * 16 + gid;          // always < 24
            const int r1 = r0 + 8;                 // pad when mt==1
            s_as[r0 * HN + head] = sa0; s_ad[r0 * HN + head] = sd0;
            if (r1 < JN) { s_as[r1 * HN + head] = sa1; s_ad[r1 * HN + head] = sd1; }
        }
    }
    __syncthreads();

    // ---- per-edge scores with leaky_relu(0.2) ----
    for (int idx = tid; idx < E * HN; idx += TPB) {
        const int e = idx >> 2, hh = idx & 3;
        float sc = s_as[s_src[e] * HN + hh] + s_ad[s_dst[e] * HN + hh];
        s_sc[e * HN + hh] = (sc >= 0.f) ? sc : 0.2f * sc;
    }
    __syncthreads();

    // ---- segment softmax: alpha written in place into s_sc ----
    if (tid < JN * HN) {
        const int j = tid >> 2, hh = tid & 3;
        const int cnt = s_cnt[j];
        float m = -3.402823466e38f;
        for (int t = 0; t < cnt; t++) m = fmaxf(m, s_sc[s_inc[j][t] * HN + hh]);
        float ex[4], den = 0.f;
        for (int t = 0; t < cnt; t++) {
            ex[t] = __expf(s_sc[s_inc[j][t] * HN + hh] - m);
            den += ex[t];
        }
        const float inv = 1.f / den;
        for (int t = 0; t < cnt; t++) s_sc[s_inc[j][t] * HN + hh] = ex[t] * inv;
    }
    __syncthreads();

    // ---- weighted gather + bias -> out ----
    float* og = out + (size_t)blockIdx.x * (JN * DN);
    for (int idx = tid; idx < JN * 64; idx += TPB) {
        const int j = idx >> 6, q = idx & 63;       // q: float4 column group
        const int hh = q >> 4;
        float4 o = ((const float4*)s_bias)[q];
        const int cnt = s_cnt[j];
        for (int t = 0; t < cnt; t++) {
            const int e = s_inc[j][t];
            const float a = s_sc[e * HN + hh];
            const float4 hv = *(const float4*)&hb[s_src[e] * HSTR + q * 4];
            o.x += a * hv.x; o.y += a * hv.y; o.z += a * hv.z; o.w += a * hv.w;
        }
        *(float4*)&og[(size_t)j * DN + q * 4] = o;
    }
}

extern "C" void kernel_launch(void* const* d_in, const int* in_sizes, int n_in,
                              void* d_out, int out_size) {
    const float* x        = (const float*)d_in[0];
    const float* W        = (const float*)d_in[1];
    const float* att_src  = (const float*)d_in[2];
    const float* att_dst  = (const float*)d_in[3];
    const float* bias     = (const float*)d_in[4];
    const int*   edge_idx = (const int*)d_in[5];
    float* out = (float*)d_out;

    const int E0   = in_sizes[5] / 2;            // 46
    const int grid = in_sizes[0] / (JN * DN);    // 4096

    cudaFuncSetAttribute(gat_mma_kernel, cudaFuncAttributeMaxDynamicSharedMemorySize, DYN_SMEM);
    prep_W<<<32, 256>>>(W);
    gat_mma_kernel<<<grid, TPB, DYN_SMEM>>>(x, att_src, att_dst, bias, edge_idx, out, E0);
}